// round 7
// baseline (speedup 1.0000x reference)
#include <cuda_runtime.h>
#include <cuda_bf16.h>

// targets: (64, 512, 1024) int32; live region = [:64, :64, :] (16 MiB)
// pc:      (64, 1, 64, 128) float32 (2 MiB)
// loss = -(1/N) * [ sum log(1-pc) + sum_corner cond(i,j)*(log pc - log(1-pc)) ]
// cond(i,j) = (0 < count_ij < 64); count_ij over targets[8i:8i+8, 8j:8j+8, :].
//
// Early-exit sampling (round 5) + product-log (round 6) unchanged.
// Round 7: hierarchical arrival. 512 same-address atomics serialized at the
// LTS atomic ALU (~27 cyc/op ~= 7.8us drain). Two-level counters (32x16 -> 32)
// cap per-address traffic at 32 ops. Counters monotonic, power-of-2 periods,
// 256B-padded so L1 counters land on distinct LTS slices.

#define N_PC    524288
#define GRID    512
#define THREADS 256
#define L1N     32      // l1 counters; each gets GRID/L1N = 16 arrivals/launch
#define L1PAD   64      // ints -> 256B spacing

__device__ int          g_blkcnt[GRID];       // plain stores, overwritten each replay
__device__ float        g_partial[GRID];      // plain stores, overwritten each replay
__device__ unsigned int g_done1[L1N * L1PAD]; // monotonic, zero-init at load
__device__ unsigned int g_done2;              // monotonic, zero-init at load

__global__ __launch_bounds__(THREADS) void fused_kernel(
    const float4* __restrict__ pc4,
    const int4*   __restrict__ tg4,
    const float*  __restrict__ pc,
    float*        __restrict__ out)
{
    const int tid  = threadIdx.x;
    const int bid  = blockIdx.x;
    const int wid  = tid >> 5;
    const int lane = tid & 31;

    // ---- pc loss load (always needed) issued first
    const int idx = bid * THREADS + tid;            // 0..131071
    float4 v = pc4[idx];

    // ---- warp's targets row and its patch
    const int row = bid * 8 + wid;                  // 0..4095 (= r*64 + c)
    const int r   = row >> 6;                       // 0..63 (batch)
    const int c   = row & 63;                       // 0..63 (H)

    // ---- patch sample: first 512 ints of patch (r&~7, c&~7, w=0..511) = 2KB
    const int4* samp = tg4 + (size_t)(r & ~7) * 131072u + (size_t)(c & ~7) * 256u;
    int scnt = 0;
    #pragma unroll
    for (int k = 0; k < 4; k++) {
        int4 q = samp[lane + k * 32];
        scnt += (q.x == 2) + (q.y == 2) + (q.z == 2) + (q.w == 2);
    }
    scnt = __reduce_add_sync(0xffffffffu, scnt);    // warp-uniform, patch-uniform

    int cnt;
    if (scnt >= 64) {
        cnt = 1 << 17;  // cond=0 proven; sentinel keeps patch total >= 64
    } else {
        // exact fallback: read the warp's full row (1024 ints = 256 int4)
        const int4* base = tg4 + (size_t)r * 131072u + (size_t)c * 256u;
        int t = 0;
        #pragma unroll
        for (int k = 0; k < 8; k++) {
            int4 q = base[lane + k * 32];
            t += (q.x == 2) + (q.y == 2) + (q.z == 2) + (q.w == 2);
        }
        cnt = __reduce_add_sync(0xffffffffu, t);
    }

    // ---- pc partial: one log of the product of (1-p) over 4 elements
    float prod = (1.0f - v.x) * (1.0f - v.y) * (1.0f - v.z) * (1.0f - v.w);
    float s = __logf(prod);
    #pragma unroll
    for (int o = 16; o > 0; o >>= 1)
        s += __shfl_down_sync(0xffffffffu, s, o);

    __shared__ float sp[8];
    __shared__ int   sc[8];
    if (lane == 0) { sp[wid] = s; sc[wid] = cnt; }
    __syncthreads();
    if (tid == 0) {
        float bs = 0.0f; int bc = 0;
        #pragma unroll
        for (int k = 0; k < 8; k++) { bs += sp[k]; bc += sc[k]; }
        g_partial[bid] = bs;
        g_blkcnt[bid]  = bc;   // all 8 rows of this block lie in ONE patch (i,j)
    }

    // ---- publish + hierarchical arrive
    __threadfence();
    __syncthreads();
    __shared__ unsigned int s_last;
    if (tid == 0) {
        unsigned int last2 = 0u;
        unsigned int o1 = atomicAdd(&g_done1[(bid & (L1N - 1)) * L1PAD], 1u);
        if ((o1 & 15u) == 15u) {               // l1 winner (16 arrivals/launch)
            __threadfence();
            unsigned int o2 = atomicAdd(&g_done2, 1u);
            last2 = ((o2 & 31u) == 31u) ? 1u : 0u;  // l2: 32 arrivals/launch
        }
        s_last = last2;
    }
    __syncthreads();
    if (!s_last) return;
    __threadfence();

    // ================= last block: aggregate =================
    __shared__ float  s_cond[64];
    __shared__ double s_red[8];

    // patch (i,j) -> blocks b = 8*(8i+rr) + j, rr = 0..7
    if (tid < 64) {
        const int i = tid >> 3, j = tid & 7;
        int pcnt = 0;
        #pragma unroll
        for (int rr = 0; rr < 8; rr++)
            pcnt += g_blkcnt[8 * (8 * i + rr) + j];
        s_cond[tid] = (pcnt > 0 && pcnt < 64) ? 1.0f : 0.0f;
    }
    __syncthreads();

    // base sum from 512 partials (double), 2 per thread
    double acc = (double)g_partial[tid] + (double)g_partial[tid + 256];

    // corner correction: 64 (i,j) x 64 batches, L2-hot pc reloads
    {
        const int ij = tid & 63;
        const int i  = ij >> 3, j = ij & 7;
        if (s_cond[ij] != 0.0f) {
            const int b0 = (tid >> 6) * 16;
            float csum = 0.0f;
            #pragma unroll 4
            for (int b = b0; b < b0 + 16; b++) {
                float p = pc[(size_t)b * 8192u + i * 128 + j];
                csum += __logf(p / (1.0f - p));
            }
            acc += (double)csum;
        }
    }

    #pragma unroll
    for (int o = 16; o > 0; o >>= 1)
        acc += __shfl_down_sync(0xffffffffu, acc, o);
    if (lane == 0) s_red[wid] = acc;
    __syncthreads();
    if (tid == 0) {
        double total = 0.0;
        #pragma unroll
        for (int k = 0; k < 8; k++) total += s_red[k];
        out[0] = (float)(-total / (double)N_PC);
    }
}

extern "C" void kernel_launch(void* const* d_in, const int* in_sizes, int n_in,
                              void* d_out, int out_size) {
    const float* pc;
    const int*   tg;
    if (in_sizes[0] == N_PC) {
        pc = (const float*)d_in[0];
        tg = (const int*)  d_in[1];
    } else {
        pc = (const float*)d_in[1];
        tg = (const int*)  d_in[0];
    }
    fused_kernel<<<GRID, THREADS>>>((const float4*)pc, (const int4*)tg,
                                    pc, (float*)d_out);
}

// round 8
// speedup vs baseline: 1.1323x; 1.1323x over previous
#include <cuda_runtime.h>
#include <cuda_bf16.h>

// targets: (64, 512, 1024) int32; live region = [:64, :64, :] (16 MiB)
// pc:      (64, 1, 64, 128) float32 (2 MiB)
// loss = -(1/N) * [ sum log(1-pc) + sum_corner cond(i,j)*(log pc - log(1-pc)) ]
// cond(i,j) = (0 < count_ij < 64); count_ij over targets[8i:8i+8, 8j:8j+8, :].
//
// Early-exit sampling (round 5) + product-log (round 6) unchanged.
// Round 8: GPU-scope fences on thread 0 ONLY (release/acquire chain through
// the arrival atomic + __syncthreads covers the rest of the block). Removes
// ~261k MEMBARs per launch. Single monotonic done-counter (round-7 hierarchy
// reverted: it regressed).

#define N_PC    524288
#define GRID    512      // power of two: monotonic done-counter wraps cleanly
#define THREADS 256

__device__ int          g_blkcnt[GRID];   // plain stores, overwritten each replay
__device__ float        g_partial[GRID];  // plain stores, overwritten each replay
__device__ unsigned int g_done;           // monotonic arrival counter (zero-init at load)

__global__ __launch_bounds__(THREADS) void fused_kernel(
    const float4* __restrict__ pc4,
    const int4*   __restrict__ tg4,
    const float*  __restrict__ pc,
    float*        __restrict__ out)
{
    const int tid  = threadIdx.x;
    const int bid  = blockIdx.x;
    const int wid  = tid >> 5;
    const int lane = tid & 31;

    // ---- pc loss load (always needed) issued first
    const int idx = bid * THREADS + tid;            // 0..131071
    float4 v = pc4[idx];

    // ---- warp's targets row and its patch
    const int row = bid * 8 + wid;                  // 0..4095 (= r*64 + c)
    const int r   = row >> 6;                       // 0..63 (batch)
    const int c   = row & 63;                       // 0..63 (H)

    // ---- patch sample: first 512 ints of patch (r&~7, c&~7, w=0..511) = 2KB
    const int4* samp = tg4 + (size_t)(r & ~7) * 131072u + (size_t)(c & ~7) * 256u;
    int scnt = 0;
    #pragma unroll
    for (int k = 0; k < 4; k++) {
        int4 q = samp[lane + k * 32];
        scnt += (q.x == 2) + (q.y == 2) + (q.z == 2) + (q.w == 2);
    }
    scnt = __reduce_add_sync(0xffffffffu, scnt);    // warp-uniform, patch-uniform

    int cnt;
    if (scnt >= 64) {
        cnt = 1 << 17;  // cond=0 proven; sentinel keeps patch total >= 64
    } else {
        // exact fallback: read the warp's full row (1024 ints = 256 int4)
        const int4* base = tg4 + (size_t)r * 131072u + (size_t)c * 256u;
        int t = 0;
        #pragma unroll
        for (int k = 0; k < 8; k++) {
            int4 q = base[lane + k * 32];
            t += (q.x == 2) + (q.y == 2) + (q.z == 2) + (q.w == 2);
        }
        cnt = __reduce_add_sync(0xffffffffu, t);
    }

    // ---- pc partial: one log of the product of (1-p) over 4 elements
    float prod = (1.0f - v.x) * (1.0f - v.y) * (1.0f - v.z) * (1.0f - v.w);
    float s = __logf(prod);
    #pragma unroll
    for (int o = 16; o > 0; o >>= 1)
        s += __shfl_down_sync(0xffffffffu, s, o);

    __shared__ float sp[8];
    __shared__ int   sc[8];
    if (lane == 0) { sp[wid] = s; sc[wid] = cnt; }
    __syncthreads();

    // ---- tid0: store partials, release-fence, arrive (all thread-0-local)
    __shared__ unsigned int s_last;
    if (tid == 0) {
        float bs = 0.0f; int bc = 0;
        #pragma unroll
        for (int k = 0; k < 8; k++) { bs += sp[k]; bc += sc[k]; }
        g_partial[bid] = bs;
        g_blkcnt[bid]  = bc;   // all 8 rows of this block lie in ONE patch (i,j)
        __threadfence();       // release: order the two stores before the atomic
        unsigned int old = atomicAdd(&g_done, 1u);
        s_last = ((old & (GRID - 1u)) == GRID - 1u) ? 1u : 0u;
    }
    __syncthreads();
    if (!s_last) return;

    // acquire: tid0 saw the final count; fence + block barrier propagate
    if (tid == 0) __threadfence();
    __syncthreads();

    // ================= last block: aggregate =================
    __shared__ float  s_cond[64];
    __shared__ double s_red[8];

    // patch (i,j) -> blocks b = 8*(8i+rr) + j, rr = 0..7
    if (tid < 64) {
        const int i = tid >> 3, j = tid & 7;
        int pcnt = 0;
        #pragma unroll
        for (int rr = 0; rr < 8; rr++)
            pcnt += g_blkcnt[8 * (8 * i + rr) + j];
        s_cond[tid] = (pcnt > 0 && pcnt < 64) ? 1.0f : 0.0f;
    }
    __syncthreads();

    // base sum from 512 partials (double), 2 per thread
    double acc = (double)g_partial[tid] + (double)g_partial[tid + 256];

    // corner correction: 64 (i,j) x 64 batches, L2-hot pc reloads
    {
        const int ij = tid & 63;
        const int i  = ij >> 3, j = ij & 7;
        if (s_cond[ij] != 0.0f) {
            const int b0 = (tid >> 6) * 16;
            float csum = 0.0f;
            #pragma unroll 4
            for (int b = b0; b < b0 + 16; b++) {
                float p = pc[(size_t)b * 8192u + i * 128 + j];
                csum += __logf(p / (1.0f - p));
            }
            acc += (double)csum;
        }
    }

    #pragma unroll
    for (int o = 16; o > 0; o >>= 1)
        acc += __shfl_down_sync(0xffffffffu, acc, o);
    if (lane == 0) s_red[wid] = acc;
    __syncthreads();
    if (tid == 0) {
        double total = 0.0;
        #pragma unroll
        for (int k = 0; k < 8; k++) total += s_red[k];
        out[0] = (float)(-total / (double)N_PC);
    }
}

extern "C" void kernel_launch(void* const* d_in, const int* in_sizes, int n_in,
                              void* d_out, int out_size) {
    const float* pc;
    const int*   tg;
    if (in_sizes[0] == N_PC) {
        pc = (const float*)d_in[0];
        tg = (const int*)  d_in[1];
    } else {
        pc = (const float*)d_in[1];
        tg = (const int*)  d_in[0];
    }
    fused_kernel<<<GRID, THREADS>>>((const float4*)pc, (const int4*)tg,
                                    pc, (float*)d_out);
}